// round 1
// baseline (speedup 1.0000x reference)
#include <cuda_runtime.h>
#include <cuda_bf16.h>

#define NN 320
#define DD 256

// Scratch (allocation-free: device globals)
__device__ float g_L[NN * NN];   // logits[i][j] = -||fi-fj||/2
__device__ float g_E[NN * NN];   // exp(logits)
__device__ float g_loss[NN];
__device__ float g_pos[NN];

// TABLE mapped to weights: 0->0, 1->1, 2->0.5   (7 rows x 7 cols)
__constant__ float c_W[49] = {
    // cid=-11
    0.f, 0.5f, 0.5f, 1.f,  1.f,  0.f,  1.f,
    // cid=-10
    0.f, 0.5f, 0.5f, 0.5f, 0.5f, 0.5f, 0.5f,
    // cid=-1
    0.f, 0.5f, 0.5f, 0.5f, 1.f,  0.f,  0.5f,
    // cid=0
    0.f, 0.5f, 0.5f, 0.5f, 0.5f, 0.5f, 0.5f,
    // cid=1
    0.f, 0.5f, 0.5f, 0.5f, 1.f,  0.5f, 0.5f,
    // cid=10
    0.f, 0.5f, 0.5f, 0.5f, 0.5f, 0.f,  0.5f,
    // cid=11
    0.f, 0.5f, 0.5f, 1.f,  1.f,  0.f,  1.f
};

// ---------------------------------------------------------------------------
// Kernel 1: pairwise distance -> logits L and exp(L).
// Max-subtraction in the reference is a provable no-op (row max == 0 at j==i).
// ---------------------------------------------------------------------------
__global__ void dist_kernel(const float* __restrict__ F) {
    int j = blockIdx.x * 32 + threadIdx.x;
    int i = blockIdx.y * 8 + threadIdx.y;
    const float4* a = reinterpret_cast<const float4*>(F) + i * (DD / 4);
    const float4* b = reinterpret_cast<const float4*>(F) + j * (DD / 4);
    float acc = 0.f;
#pragma unroll 16
    for (int q = 0; q < DD / 4; q++) {
        float4 x = a[q];
        float4 y = b[q];
        float d0 = x.x - y.x, d1 = x.y - y.y, d2 = x.z - y.z, d3 = x.w - y.w;
        acc += d0 * d0;
        acc += d1 * d1;
        acc += d2 * d2;
        acc += d3 * d3;
    }
    float nrm = sqrtf(acc);                 // acc >= 0; diagonal acc == +0 exactly
    float L = -0.5f * nrm;                  // TEMP = 2.0
    g_L[i * NN + j] = L;
    g_E[i * NN + j] = __expf(L);
}

// ---------------------------------------------------------------------------
// Kernel 2: per-anchor loss. One block per anchor k (320 blocks x 320 threads).
// Warp w handles rows i = w, w+10, ..., w+310; lanes split j (10 regs each).
// ---------------------------------------------------------------------------
__global__ void loss_kernel(const float* __restrict__ yt, const int* __restrict__ ye) {
    __shared__ float s_pld[NN];
    __shared__ int   s_ev[NN];
    __shared__ float s_W[49];
    __shared__ float s_sum[10];
    __shared__ float s_np[10];

    int k = blockIdx.x;
    int tid = threadIdx.x;
    float tk = __ldg(&yt[k]);
    s_pld[tid] = yt[tid] - tk;
    s_ev[tid] = ye[tid];
    if (tid < 49) s_W[tid] = c_W[tid];
    __syncthreads();

    int ek = s_ev[k];
    int lane = tid & 31;
    int w = tid >> 5;

    // Register-cache this lane's 10 j-columns (j = r*32 + lane)
    float pj[10];
    int ej3[10];
#pragma unroll
    for (int r = 0; r < 10; r++) {
        int j = r * 32 + lane;
        pj[r] = s_pld[j];
        ej3[r] = s_ev[j] * 3;
    }

    float accs = 0.f;   // sum of valid logp (uniform across lanes after reduce)
    float accn = 0.f;   // count of valid rows

    for (int iw = 0; iw < 32; iw++) {
        int i = w + iw * 10;
        float pi = s_pld[i];
        int ei = s_ev[i];
        float a = fabsf(pi);
        float na = -a;

        // cid = (e_i + 10*e_k) * sign(pld_i); cidx = searchsorted(CASE_VALS, cid)
        int base = ei + 10 * ek;
        int cid = (pi > 0.f) ? base : ((pi < 0.f) ? -base : 0);
        int cidx = (cid == -11) ? 0 : (cid == -10) ? 1 : (cid == -1) ? 2 :
                   (cid == 0)   ? 3 : (cid == 1)   ? 4 : (cid == 10) ? 5 : 6;
        const float* Wr = s_W + cidx * 7;

        // Preload E row chunk (coalesced, MLP=10)
        const float* Erow = g_E + i * NN;
        float Ev[10];
#pragma unroll
        for (int r = 0; r < 10; r++) Ev[r] = Erow[r * 32 + lane];

        float denom = 0.f;
#pragma unroll
        for (int r = 0; r < 10; r++) {
            float p = pj[r];
            // td: pj > a -> 3 ; -pj > a (== pj < -a) -> 1 ; |pj|>0 -> 2 ; else 0
            int td = (p > a) ? 3 : ((p < na) ? 1 : 2);
            int v = (p != 0.f) ? (td + ej3[r]) : 0;   // vidx (neg>3 ? neg-7 : neg)
            int j = r * 32 + lane;
            float wgt = (j == i) ? 0.f : Wr[v];        // eye mask
            denom += wgt * Ev[r];
        }

        // Warp reduce (butterfly -> uniform across lanes)
#pragma unroll
        for (int s = 16; s > 0; s >>= 1)
            denom += __shfl_xor_sync(0xffffffffu, denom, s);

        // valid == (sum of weights > 0); E > 0 strictly so denom > 0 iff any w > 0.
        // Row i==k is fully masked by keep[] in the reference -> force invalid.
        bool valid = (denom > 0.f) && (i != k);
        if (valid) {
            float logit = __ldg(&g_L[i * NN + k]);
            accs += logit - __logf(denom);
            accn += 1.f;
        }
    }

    if (lane == 0) { s_sum[w] = accs; s_np[w] = accn; }
    __syncthreads();
    if (tid == 0) {
        float S = 0.f, Q = 0.f;
#pragma unroll
        for (int q = 0; q < 10; q++) { S += s_sum[q]; Q += s_np[q]; }
        g_loss[k] = (Q > 0.f) ? (-S / Q) : 0.f;
        g_pos[k]  = (Q > 0.f) ? 1.f : 0.f;
    }
}

// ---------------------------------------------------------------------------
// Kernel 3: final scalar = sum(loss) / sum(has_pos)
// ---------------------------------------------------------------------------
__global__ void finalize_kernel(float* __restrict__ out) {
    __shared__ float s_a[10];
    __shared__ float s_b[10];
    int tid = threadIdx.x;
    int lane = tid & 31;
    int w = tid >> 5;
    float a = g_loss[tid];
    float b = g_pos[tid];
#pragma unroll
    for (int s = 16; s > 0; s >>= 1) {
        a += __shfl_xor_sync(0xffffffffu, a, s);
        b += __shfl_xor_sync(0xffffffffu, b, s);
    }
    if (lane == 0) { s_a[w] = a; s_b[w] = b; }
    __syncthreads();
    if (tid == 0) {
        float S = 0.f, P = 0.f;
#pragma unroll
        for (int q = 0; q < 10; q++) { S += s_a[q]; P += s_b[q]; }
        out[0] = S / P;
    }
}

extern "C" void kernel_launch(void* const* d_in, const int* in_sizes, int n_in,
                              void* d_out, int out_size) {
    const float* features = (const float*)d_in[0];   // [320, 256] f32
    const float* y_times  = (const float*)d_in[1];   // [320] f32
    const int*   y_events = (const int*)d_in[2];     // [320] i32
    float* out = (float*)d_out;

    dim3 dgrid(NN / 32, NN / 8);
    dim3 dblk(32, 8);
    dist_kernel<<<dgrid, dblk>>>(features);
    loss_kernel<<<NN, NN>>>(y_times, y_events);
    finalize_kernel<<<1, NN>>>(out);
}

// round 2
// speedup vs baseline: 2.9623x; 2.9623x over previous
#include <cuda_runtime.h>
#include <cuda_bf16.h>

#define NN 320
#define DD 256

// Scratch (allocation-free device globals)
__device__ float  g_L[NN * NN];     // logits[i][j] = -||fi-fj||/2
__device__ float  g_E[NN * NN];     // exp(logits)
__device__ float  g_ys[NN];         // sorted y_times
__device__ int    g_perm[NN];       // sorted order -> original index
__device__ int    g_se[NN];         // event of sorted element
__device__ int    g_gt[NN];         // per k: first sorted m with ys[m]-yk > 0
__device__ int    g_geq[NN];        // per k: first sorted m with !(ys[m]-yk < 0)
__device__ float2 g_pair[NN * NN];  // (logp_or_0, valid) per (i,k)
__device__ float2 g_blk[10];

// TABLE rows packed as 2-bit weight codes c in {0,1,2}, weight = c*0.5:
// table value t: 0->c0, 1->c2 (weight 1.0), 2->c1 (weight 0.5). Bits [2v+1:2v].
__constant__ int c_rb[7] = {8852, 5460, 4692, 5460, 5716, 4436, 8852};

// first index m in [0,NN) with (ys[m]-yk > x); NN if none. Monotone predicate
// (FP subtraction is monotone in ys[m]) -> exact match to reference compares.
__device__ __forceinline__ int pp_greater(const float* ys, float yk, float x) {
    int first = 0, count = NN;
    while (count > 0) {
        int half = count >> 1, mid = first + half;
        if (!(ys[mid] - yk > x)) { first = mid + 1; count -= half + 1; }
        else count = half;
    }
    return first;
}
// first index m with !(ys[m]-yk < x)
__device__ __forceinline__ int pp_notless(const float* ys, float yk, float x) {
    int first = 0, count = NN;
    while (count > 0) {
        int half = count >> 1, mid = first + half;
        if (ys[mid] - yk < x) { first = mid + 1; count -= half + 1; }
        else count = half;
    }
    return first;
}

// ---------------------------------------------------------------------------
// Kernel 1: bitonic sort of y (value<<32|idx keys; nonneg floats sort as uints)
// + per-k equal-run bounds gt/geq.
// ---------------------------------------------------------------------------
__global__ void sort_kernel(const float* __restrict__ yt, const int* __restrict__ ye) {
    __shared__ unsigned long long keys[512];
    __shared__ float sy[NN];
    int t = threadIdx.x;
    keys[t] = (t < NN) ? ((((unsigned long long)__float_as_uint(yt[t])) << 32) | (unsigned)t)
                       : 0xFFFFFFFFFFFFFFFFULL;
    __syncthreads();
    for (int k = 2; k <= 512; k <<= 1) {
        for (int j = k >> 1; j > 0; j >>= 1) {
            int ixj = t ^ j;
            if (ixj > t) {
                unsigned long long a = keys[t], b = keys[ixj];
                bool up = ((t & k) == 0);
                if ((a > b) == up) { keys[t] = b; keys[ixj] = a; }
            }
            __syncthreads();
        }
    }
    if (t < NN) {
        unsigned long long kk = keys[t];
        float v = __uint_as_float((unsigned)(kk >> 32));
        int idx = (int)(kk & 0xFFFFFFFFu);
        g_ys[t] = v;
        g_perm[t] = idx;
        g_se[t] = ye[idx];
        sy[t] = v;
    }
    __syncthreads();
    if (t < NN) {
        float yk = yt[t];
        g_gt[t]  = pp_greater(sy, yk, 0.0f);
        g_geq[t] = pp_notless(sy, yk, 0.0f);
    }
}

// ---------------------------------------------------------------------------
// Kernel 2: pairwise distances, smem-tiled 32x32, 2x2 register micro-tiles.
// Row max subtraction in reference is a no-op (diag logit == 0 == row max).
// ---------------------------------------------------------------------------
__global__ void dist_kernel(const float* __restrict__ F) {
    __shared__ float sA[32][34];   // [d][i], pad 34 keeps LDS.64 alignment
    __shared__ float sB[32][34];
    int tx = threadIdx.x, ty = threadIdx.y;        // 16 x 16
    int tid = ty * 16 + tx;
    int bi = blockIdx.y * 32, bj = blockIdx.x * 32;
    int lrow = tid >> 3;          // 0..31
    int lcol = (tid & 7) << 2;    // 0,4,...,28
    float a00 = 0.f, a01 = 0.f, a10 = 0.f, a11 = 0.f;
    for (int c = 0; c < 8; c++) {
        int d0 = c * 32;
        float4 av = *(const float4*)(F + (bi + lrow) * DD + d0 + lcol);
        float4 bv = *(const float4*)(F + (bj + lrow) * DD + d0 + lcol);
        __syncthreads();
        sA[lcol + 0][lrow] = av.x; sA[lcol + 1][lrow] = av.y;
        sA[lcol + 2][lrow] = av.z; sA[lcol + 3][lrow] = av.w;
        sB[lcol + 0][lrow] = bv.x; sB[lcol + 1][lrow] = bv.y;
        sB[lcol + 2][lrow] = bv.z; sB[lcol + 3][lrow] = bv.w;
        __syncthreads();
#pragma unroll
        for (int dd = 0; dd < 32; dd++) {
            float x0 = sA[dd][2 * ty], x1 = sA[dd][2 * ty + 1];
            float y0 = sB[dd][2 * tx], y1 = sB[dd][2 * tx + 1];
            float d;
            d = x0 - y0; a00 += d * d;
            d = x0 - y1; a01 += d * d;
            d = x1 - y0; a10 += d * d;
            d = x1 - y1; a11 += d * d;
        }
    }
    int i0 = bi + 2 * ty, j0 = bj + 2 * tx;
    float L;
    L = -0.5f * sqrtf(a00); g_L[i0 * NN + j0]           = L; g_E[i0 * NN + j0]           = __expf(L);
    L = -0.5f * sqrtf(a01); g_L[i0 * NN + j0 + 1]       = L; g_E[i0 * NN + j0 + 1]       = __expf(L);
    L = -0.5f * sqrtf(a10); g_L[(i0 + 1) * NN + j0]     = L; g_E[(i0 + 1) * NN + j0]     = __expf(L);
    L = -0.5f * sqrtf(a11); g_L[(i0 + 1) * NN + j0 + 1] = L; g_E[(i0 + 1) * NN + j0 + 1] = __expf(L);
}

// ---------------------------------------------------------------------------
// Kernel 3: per-row-i block. Build class-split prefix sums of E over sorted-j
// (diag zeroed), then each thread k: 2 binary searches + prefix assembly.
// O(N^2 log N) total, replacing the O(N^3) loop.
// ---------------------------------------------------------------------------
__global__ void loss_kernel(const float* __restrict__ yt, const int* __restrict__ ye) {
    __shared__ float  s_ys[NN];
    __shared__ float  s_P0[NN + 1], s_P1[NN + 1];
    __shared__ float2 s_scan[2][NN];
    __shared__ int    s_rb[7];
    int i = blockIdx.x;
    int t = threadIdx.x;
    if (t < 7) s_rb[t] = c_rb[t];
    s_ys[t] = g_ys[t];
    int pj = g_perm[t];
    float Ev = (pj == i) ? 0.f : g_E[i * NN + pj];   // eye mask folded here
    int cls = g_se[t];
    float2 v; v.x = cls ? 0.f : Ev; v.y = cls ? Ev : 0.f;
    s_scan[0][t] = v;
    __syncthreads();
    // Hillis-Steele inclusive scan (9 rounds)
    int src = 0;
    for (int off = 1; off < NN; off <<= 1) {
        float2 x = s_scan[src][t];
        if (t >= off) { float2 y2 = s_scan[src][t - off]; x.x += y2.x; x.y += y2.y; }
        s_scan[src ^ 1][t] = x;
        src ^= 1;
        __syncthreads();
    }
    float2 inc = s_scan[src][t];
    s_P0[t + 1] = inc.x; s_P1[t + 1] = inc.y;
    if (t == 0) { s_P0[0] = 0.f; s_P1[0] = 0.f; }
    __syncthreads();

    int k = t;
    float yi = yt[i]; int ei = ye[i];
    float yk = yt[k]; int ek = ye[k];
    float pi = yi - yk;
    float a = fabsf(pi), na = -a;
    int base = ei + 10 * ek;
    int cid = (pi > 0.f) ? base : ((pi < 0.f) ? -base : 0);
    int cidx = (cid == -11) ? 0 : (cid == -10) ? 1 : (cid == -1) ? 2 :
               (cid == 0)   ? 3 : (cid == 1)   ? 4 : (cid == 10) ? 5 : 6;
    int rb = s_rb[cidx];
    int hi = pp_greater(s_ys, yk, a);    // first p >  a  (upper region start)
    int lo = pp_notless(s_ys, yk, na);   // first p >= -a (lower region end)
    int gt = g_gt[k], geq = g_geq[k];    // equal run [geq, gt): p == 0 -> weight 0
    float Phi0 = s_P0[hi], Phi1 = s_P1[hi];
    float Plo0 = s_P0[lo], Plo1 = s_P1[lo];
    float SU0 = s_P0[NN] - Phi0, SU1 = s_P1[NN] - Phi1;
    float SL0 = Plo0,            SL1 = Plo1;
    float SM0 = (Phi0 - Plo0) - (s_P0[gt] - s_P0[geq]);
    float SM1 = (Phi1 - Plo1) - (s_P1[gt] - s_P1[geq]);
    // weight codes: v = td + 3*e; td=1 lower, 2 middle, 3 upper
    float w10 = (float)((rb >> 2)  & 3), w20 = (float)((rb >> 4)  & 3), w30 = (float)((rb >> 6)  & 3);
    float w11 = (float)((rb >> 8)  & 3), w21 = (float)((rb >> 10) & 3), w31 = (float)((rb >> 12) & 3);
    float denom = 0.5f * (w10 * SL0 + w11 * SL1 + w20 * SM0 + w21 * SM1 + w30 * SU0 + w31 * SU1);
    bool valid = (denom > 0.f) && (i != k);   // row i==k fully masked in reference
    float res = valid ? (g_L[i * NN + k] - __logf(denom)) : 0.f;
    float2 outp; outp.x = res; outp.y = valid ? 1.f : 0.f;
    g_pair[i * NN + k] = outp;
}

// ---------------------------------------------------------------------------
// Finalize stage 1: block b reduces over i for k in [32b, 32b+32), computes
// per-k loss, and a per-block partial (sum_loss, sum_has_pos). Deterministic.
// ---------------------------------------------------------------------------
__global__ void fin1_kernel() {
    __shared__ float2 red[NN];
    int b = blockIdx.x, t = threadIdx.x;
    int kk = t & 31;
    int ig = t >> 5;          // 0..9
    int k = b * 32 + kk;
    float s = 0.f, c = 0.f;
#pragma unroll 4
    for (int q = 0; q < 32; q++) {
        int i = ig * 32 + q;
        float2 v = g_pair[i * NN + k];
        s += v.x; c += v.y;
    }
    red[t] = make_float2(s, c);
    __syncthreads();
    if (t < 32) {
        float S = 0.f, C = 0.f;
#pragma unroll
        for (int g = 0; g < 10; g++) { float2 v = red[g * 32 + t]; S += v.x; C += v.y; }
        float lk = (C > 0.f) ? (-S / C) : 0.f;
        float hp = (C > 0.f) ? 1.f : 0.f;
#pragma unroll
        for (int sh = 16; sh > 0; sh >>= 1) {
            lk += __shfl_xor_sync(0xffffffffu, lk, sh);
            hp += __shfl_xor_sync(0xffffffffu, hp, sh);
        }
        if (t == 0) g_blk[b] = make_float2(lk, hp);
    }
}

__global__ void fin2_kernel(float* __restrict__ out) {
    float S = 0.f, P = 0.f;
#pragma unroll
    for (int b = 0; b < 10; b++) { float2 v = g_blk[b]; S += v.x; P += v.y; }
    out[0] = S / P;
}

extern "C" void kernel_launch(void* const* d_in, const int* in_sizes, int n_in,
                              void* d_out, int out_size) {
    const float* features = (const float*)d_in[0];   // [320, 256] f32
    const float* y_times  = (const float*)d_in[1];   // [320] f32
    const int*   y_events = (const int*)d_in[2];     // [320] i32
    float* out = (float*)d_out;

    sort_kernel<<<1, 512>>>(y_times, y_events);
    dist_kernel<<<dim3(10, 10), dim3(16, 16)>>>(features);
    loss_kernel<<<NN, NN>>>(y_times, y_events);
    fin1_kernel<<<10, NN>>>();
    fin2_kernel<<<1, 1>>>(out);
}

// round 3
// speedup vs baseline: 3.4937x; 1.1794x over previous
#include <cuda_runtime.h>
#include <cuda_bf16.h>

#define NN 320
#define DD 256

// Scratch (allocation-free device globals)
__device__ float  g_L[NN * NN];       // logits (bit-exact symmetric)
__device__ float  g_E[NN * NN];       // exp(logits)
__device__ float  g_ys[NN];           // sorted y_times
__device__ int    g_perm[NN];         // sorted pos -> original index
__device__ int    g_se[NN];           // event class in sorted order
__device__ int    g_gt[NN];           // per k: first sorted m with ys[m]-yk > 0 (as count)
__device__ int    g_geq[NN];          // per k: first sorted m with !(ys[m]-yk < 0)
__device__ float2 g_P[NN * (NN + 1)]; // per-row class-split E prefix sums (sorted order)
__device__ int    g_cnt[NN + 1];      // class-count prefix, packed c1<<10 | c0
__device__ float  g_loss[NN];
__device__ float  g_pos[NN];
__device__ int    g_ctr;

// TABLE rows packed: weight code c in {0,1,2} (weight = c*0.5) at bits [2v+1:2v],
// v = td + 3*e, td in {1(lower),2(middle),3(upper)}.
__constant__ int c_rb[7] = {8852, 5460, 4692, 5460, 5716, 4436, 8852};

// ---------------------------------------------------------------------------
// Kernel 1: distances (blocks 0..99) + exact rank sort / run bounds (100,101).
// Row-max subtraction in reference is a provable no-op (diag logit == row max).
// ---------------------------------------------------------------------------
__global__ void dist_kernel(const float* __restrict__ F,
                            const float* __restrict__ yt,
                            const int* __restrict__ ye) {
    __shared__ float sA[32][34];
    __shared__ float sB[32][34];
    __shared__ float s_y[NN];
    int tx = threadIdx.x, ty = threadIdx.y;       // 16 x 16
    int tid = ty * 16 + tx;
    int b = blockIdx.x;

    if (b >= 100) {
        // --- sort / bounds block: 160 anchors each, O(N) count per anchor ---
        for (int e = tid; e < NN; e += 256) s_y[e] = yt[e];
        __syncthreads();
        if (tid < 160) {
            int e = (b - 100) * 160 + tid;
            float v = s_y[e];
            int rank = 0, gt = 0, geq = 0;
#pragma unroll 8
            for (int j = 0; j < NN; j++) {
                float w = s_y[j];
                float d = w - v;                       // exact same op as reference pld
                rank += (w < v) || (w == v && j < e);  // unique tie-broken rank
                gt  += !(d > 0.0f);
                geq += (d < 0.0f);
            }
            g_ys[rank] = v; g_perm[rank] = e; g_se[rank] = __ldg(&ye[e]);
            g_gt[e] = gt; g_geq[e] = geq;
        }
        return;
    }

    int bi = (b / 10) * 32, bj = (b % 10) * 32;
    int lrow = tid >> 3;
    int lcol = (tid & 7) << 2;
    float a00 = 0.f, a01 = 0.f, a10 = 0.f, a11 = 0.f;
    for (int c = 0; c < 8; c++) {
        int d0 = c * 32;
        float4 av = *(const float4*)(F + (bi + lrow) * DD + d0 + lcol);
        float4 bv = *(const float4*)(F + (bj + lrow) * DD + d0 + lcol);
        __syncthreads();
        sA[lcol + 0][lrow] = av.x; sA[lcol + 1][lrow] = av.y;
        sA[lcol + 2][lrow] = av.z; sA[lcol + 3][lrow] = av.w;
        sB[lcol + 0][lrow] = bv.x; sB[lcol + 1][lrow] = bv.y;
        sB[lcol + 2][lrow] = bv.z; sB[lcol + 3][lrow] = bv.w;
        __syncthreads();
#pragma unroll
        for (int dd = 0; dd < 32; dd++) {
            float x0 = sA[dd][2 * ty], x1 = sA[dd][2 * ty + 1];
            float y0 = sB[dd][2 * tx], y1 = sB[dd][2 * tx + 1];
            float d;
            d = x0 - y0; a00 += d * d;
            d = x0 - y1; a01 += d * d;
            d = x1 - y0; a10 += d * d;
            d = x1 - y1; a11 += d * d;
        }
    }
    int i0 = bi + 2 * ty, j0 = bj + 2 * tx;
    float L;
    L = -0.5f * sqrtf(a00); g_L[i0 * NN + j0]           = L; g_E[i0 * NN + j0]           = __expf(L);
    L = -0.5f * sqrtf(a01); g_L[i0 * NN + j0 + 1]       = L; g_E[i0 * NN + j0 + 1]       = __expf(L);
    L = -0.5f * sqrtf(a10); g_L[(i0 + 1) * NN + j0]     = L; g_E[(i0 + 1) * NN + j0]     = __expf(L);
    L = -0.5f * sqrtf(a11); g_L[(i0 + 1) * NN + j0 + 1] = L; g_E[(i0 + 1) * NN + j0 + 1] = __expf(L);
}

// ---------------------------------------------------------------------------
// Kernel 2: per-row class-split prefix sums (warp-shuffle scan). Block 0 also
// builds the global class-count prefix and resets the completion counter.
// ---------------------------------------------------------------------------
__global__ void scan_kernel() {
    __shared__ float ws0[10], ws1[10], wo0[10], wo1[10];
    __shared__ int   wsi[10], woi[10];
    int i = blockIdx.x, t = threadIdx.x;
    int lane = t & 31, w = t >> 5;
    if (i == 0 && t == 0) g_ctr = 0;

    int pj = g_perm[t];
    int cls = g_se[t];
    float Ev = (pj == i) ? 0.f : __ldg(&g_E[i * NN + pj]);   // eye mask folded
    float x0 = cls ? 0.f : Ev;
    float x1 = cls ? Ev : 0.f;
    int   xc = cls ? (1 << 10) : 1;   // class-count (block 0 only uses it)

#pragma unroll
    for (int off = 1; off < 32; off <<= 1) {
        float a0 = __shfl_up_sync(0xffffffffu, x0, off);
        float a1 = __shfl_up_sync(0xffffffffu, x1, off);
        int   ac = __shfl_up_sync(0xffffffffu, xc, off);
        if (lane >= off) { x0 += a0; x1 += a1; xc += ac; }
    }
    if (lane == 31) { ws0[w] = x0; ws1[w] = x1; wsi[w] = xc; }
    __syncthreads();
    if (t == 0) {
        float r0 = 0.f, r1 = 0.f; int ri = 0;
#pragma unroll
        for (int q = 0; q < 10; q++) {
            wo0[q] = r0; wo1[q] = r1; woi[q] = ri;
            r0 += ws0[q]; r1 += ws1[q]; ri += wsi[q];
        }
    }
    __syncthreads();
    x0 += wo0[w]; x1 += wo1[w];
    float2* Prow = g_P + i * (NN + 1);
    Prow[t + 1] = make_float2(x0, x1);
    if (t == 0) Prow[0] = make_float2(0.f, 0.f);
    if (i == 0) {
        g_cnt[t + 1] = xc + woi[w];
        if (t == 0) g_cnt[0] = 0;
    }
}

// ---------------------------------------------------------------------------
// Kernel 3: block per anchor k, thread per row i. 2 binary searches + prefix
// assembly; exact integer-count validity; block reduce -> loss_k; last block
// done produces the final scalar (deterministic fixed-order reduction).
// ---------------------------------------------------------------------------
__global__ void lossk_kernel(const float* __restrict__ yt,
                             const int* __restrict__ ye,
                             float* __restrict__ out) {
    __shared__ float s_ys[NN];
    __shared__ int   s_cnt[NN + 1];
    __shared__ int   s_rb[7];
    __shared__ float rS[10], rC[10];
    __shared__ int   s_last;

    int k = blockIdx.x, t = threadIdx.x;
    int lane = t & 31, w = t >> 5;
    s_ys[t] = g_ys[t];
    s_cnt[t] = g_cnt[t];
    if (t == 0) s_cnt[NN] = g_cnt[NN];
    if (t < 7) s_rb[t] = c_rb[t];
    __syncthreads();

    float yk = __ldg(&yt[k]);
    int   ek = __ldg(&ye[k]);
    int   gt = g_gt[k], geq = g_geq[k];

    int i = t;
    float yi = yt[i];
    int   ei = ye[i];
    float pi = yi - yk;
    float a = fabsf(pi), na = -a;

    int base = ei + 10 * ek;
    int cid = (pi > 0.f) ? base : ((pi < 0.f) ? -base : 0);
    int cidx = (cid == -11) ? 0 : (cid == -10) ? 1 : (cid == -1) ? 2 :
               (cid == 0)   ? 3 : (cid == 1)   ? 4 : (cid == 10) ? 5 : 6;
    int rb = s_rb[cidx];

    // hi: first m with ys[m]-yk > a   (identical float expr as reference)
    int first = 0, count = NN;
    while (count > 0) {
        int half = count >> 1, mid = first + half;
        if (!(s_ys[mid] - yk > a)) { first = mid + 1; count -= half + 1; }
        else count = half;
    }
    int hi = first;
    // lo: first m with !(ys[m]-yk < -a)
    first = 0; count = NN;
    while (count > 0) {
        int half = count >> 1, mid = first + half;
        if (s_ys[mid] - yk < na) { first = mid + 1; count -= half + 1; }
        else count = half;
    }
    int lo = first;

    const float2* Prow = g_P + i * (NN + 1);
    float2 Pend = Prow[NN], Phi = Prow[hi], Plo = Prow[lo];
    float2 Pgt = Prow[gt], Pgq = Prow[geq];
    float SU0 = Pend.x - Phi.x, SU1 = Pend.y - Phi.y;
    float SL0 = Plo.x,          SL1 = Plo.y;
    float SM0 = (Phi.x - Plo.x) - (Pgt.x - Pgq.x);
    float SM1 = (Phi.y - Plo.y) - (Pgt.y - Pgq.y);

    float w10 = (float)((rb >> 2)  & 3), w20 = (float)((rb >> 4)  & 3), w30 = (float)((rb >> 6)  & 3);
    float w11 = (float)((rb >> 8)  & 3), w21 = (float)((rb >> 10) & 3), w31 = (float)((rb >> 12) & 3);
    float denom = 0.5f * (w10 * SL0 + w11 * SL1 + w20 * SM0 + w21 * SM1 + w30 * SU0 + w31 * SU1);

    // Exact integer validity: counts of positive-weight elements.
    int cU = s_cnt[NN] - s_cnt[hi];
    int cL = s_cnt[lo];
    int cM = (s_cnt[hi] - s_cnt[lo]) - (s_cnt[gt] - s_cnt[geq]);
    if (pi != 0.f) cM -= (ei ? (1 << 10) : 1);   // i sits in middle, weight 0 (eye)
    int nz = rb | (rb >> 1);
    int vsum = ((nz >> 2) & 1) * (cL & 1023) + ((nz >> 8)  & 1) * (cL >> 10)
             + ((nz >> 4) & 1) * (cM & 1023) + ((nz >> 10) & 1) * (cM >> 10)
             + ((nz >> 6) & 1) * (cU & 1023) + ((nz >> 12) & 1) * (cU >> 10);
    bool valid = (vsum > 0) && (i != k);

    float res = valid ? (__ldg(&g_L[k * NN + i]) - __logf(denom)) : 0.f;  // L symmetric
    float c   = valid ? 1.f : 0.f;

#pragma unroll
    for (int sh = 16; sh > 0; sh >>= 1) {
        res += __shfl_xor_sync(0xffffffffu, res, sh);
        c   += __shfl_xor_sync(0xffffffffu, c,   sh);
    }
    if (lane == 0) { rS[w] = res; rC[w] = c; }
    __syncthreads();
    if (t == 0) {
        float S = 0.f, C = 0.f;
#pragma unroll
        for (int q = 0; q < 10; q++) { S += rS[q]; C += rC[q]; }
        g_loss[k] = (C > 0.f) ? (-S / C) : 0.f;
        g_pos[k]  = (C > 0.f) ? 1.f : 0.f;
        __threadfence();
        int old = atomicAdd(&g_ctr, 1);
        s_last = (old == NN - 1);
    }
    __syncthreads();
    if (s_last) {
        float sa = g_loss[t], sb = g_pos[t];
#pragma unroll
        for (int sh = 16; sh > 0; sh >>= 1) {
            sa += __shfl_xor_sync(0xffffffffu, sa, sh);
            sb += __shfl_xor_sync(0xffffffffu, sb, sh);
        }
        if (lane == 0) { rS[w] = sa; rC[w] = sb; }
        __syncthreads();
        if (t == 0) {
            float S = 0.f, P = 0.f;
#pragma unroll
            for (int q = 0; q < 10; q++) { S += rS[q]; P += rC[q]; }
            out[0] = S / P;
        }
    }
}

extern "C" void kernel_launch(void* const* d_in, const int* in_sizes, int n_in,
                              void* d_out, int out_size) {
    const float* features = (const float*)d_in[0];   // [320, 256] f32
    const float* y_times  = (const float*)d_in[1];   // [320] f32
    const int*   y_events = (const int*)d_in[2];     // [320] i32
    float* out = (float*)d_out;

    dist_kernel<<<102, dim3(16, 16)>>>(features, y_times, y_events);
    scan_kernel<<<NN, NN>>>();
    lossk_kernel<<<NN, NN>>>(y_times, y_events, out);
}